// round 1
// baseline (speedup 1.0000x reference)
#include <cuda_runtime.h>

#define N_NODES 50000

// Scratch (allocation-free: __device__ globals)
__device__ __align__(128) float g_deg [N_NODES];
__device__ __align__(128) float g_dis [N_NODES];
__device__ __align__(128) float g_agg1[N_NODES * 64];
__device__ __align__(128) float g_h1  [N_NODES * 128];
__device__ __align__(128) float g_agg2[N_NODES * 128];
__device__ __align__(128) float g_h2  [N_NODES * 128];
__device__ __align__(128) float g_A   [N_NODES * 128];
__device__ __align__(128) float g_B   [N_NODES * 128];

__device__ __forceinline__ void red_add_v4(float* p, float4 v) {
    asm volatile("red.global.add.v4.f32 [%0], {%1,%2,%3,%4};"
                 :: "l"(p), "f"(v.x), "f"(v.y), "f"(v.z), "f"(v.w) : "memory");
}

// deg[i] = 1 (self loop)
__global__ void k_deg_init(int n) {
    int i = blockIdx.x * blockDim.x + threadIdx.x;
    if (i < n) g_deg[i] = 1.0f;
}

// deg[row[e]] += 1
__global__ void k_deg_count(const int* __restrict__ row, int E) {
    int e = blockIdx.x * blockDim.x + threadIdx.x;
    if (e < E) atomicAdd(&g_deg[row[e]], 1.0f);
}

// dis[i] = deg^-0.5 ; agg1[i] = x[i] * dis[i]^2   (self-loop contribution folded in)
__global__ void k_dis_agg1init(const float* __restrict__ x, int n) {
    int t = blockIdx.x * blockDim.x + threadIdx.x;
    int i = t >> 4, j = t & 15;          // 16 float4 per node (64 floats)
    if (i >= n) return;
    float d = rsqrtf(g_deg[i]);
    if (j == 0) g_dis[i] = d;
    float s = d * d;
    float4 v = ((const float4*)x)[i * 16 + j];
    v.x *= s; v.y *= s; v.z *= s; v.w *= s;
    ((float4*)g_agg1)[i * 16 + j] = v;
}

// agg1[col] += x[row] * dis[row]*dis[col]     (16 threads / edge, v4 red)
__global__ void k_scatter1(const float* __restrict__ x, const int* __restrict__ ei, int E) {
    int t = blockIdx.x * blockDim.x + threadIdx.x;
    int e = t >> 4, j = t & 15;
    if (e >= E) return;
    int r = __ldg(ei + e);
    int c = __ldg(ei + E + e);
    float nrm = g_dis[r] * g_dis[c];
    float4 v = ((const float4*)x)[r * 16 + j];
    v.x *= nrm; v.y *= nrm; v.z *= nrm; v.w *= nrm;
    red_add_v4(&g_agg1[c * 64 + j * 4], v);
}

// agg2[i] = h1[i] * dis[i]^2
__global__ void k_agg2init(int n) {
    int t = blockIdx.x * blockDim.x + threadIdx.x;
    int i = t >> 5, j = t & 31;          // 32 float4 per node (128 floats)
    if (i >= n) return;
    float d = g_dis[i];
    float s = d * d;
    float4 v = ((const float4*)g_h1)[i * 32 + j];
    v.x *= s; v.y *= s; v.z *= s; v.w *= s;
    ((float4*)g_agg2)[i * 32 + j] = v;
}

// agg2[col] += h1[row] * dis[row]*dis[col]    (32 threads / edge)
__global__ void k_scatter2(const int* __restrict__ ei, int E) {
    int t = blockIdx.x * blockDim.x + threadIdx.x;
    int e = t >> 5, j = t & 31;
    if (e >= E) return;
    int r = __ldg(ei + e);
    int c = __ldg(ei + E + e);
    float nrm = g_dis[r] * g_dis[c];
    float4 v = ((const float4*)g_h1)[r * 32 + j];
    v.x *= nrm; v.y *= nrm; v.z *= nrm; v.w *= nrm;
    red_add_v4(&g_agg2[c * 128 + j * 4], v);
}

// C[M,128] = act(A[M,K] @ W[K,128] + bias). Block: 64 rows x 128 cols, 256 thr.
template <int K>
__global__ void gemm_k(const float* __restrict__ A, const float* __restrict__ W,
                       const float* __restrict__ bias, float* __restrict__ C,
                       int M, int relu) {
    __shared__ float As[64 * 64];     // 16KB
    __shared__ float Ws[64 * 128];    // 32KB
    int tid  = threadIdx.x;
    int row0 = blockIdx.x * 64;
    int c0   = tid & 31;              // float4 column index (c = 4*c0)
    int r0   = (tid >> 5) * 8;        // 8-row group

    float4 bv = make_float4(0.f, 0.f, 0.f, 0.f);
    if (bias) bv = ((const float4*)bias)[c0];
    float4 acc[8];
#pragma unroll
    for (int i = 0; i < 8; i++) acc[i] = bv;

    for (int kc = 0; kc < K; kc += 64) {
        // load W chunk [64,128]
        for (int i = tid; i < 64 * 32; i += 256) {
            int k = i >> 5, cc = i & 31;
            ((float4*)Ws)[i] = ((const float4*)(W + (kc + k) * 128))[cc];
        }
        // load A chunk [64,64]
        for (int i = tid; i < 64 * 16; i += 256) {
            int r = i >> 4, kk = i & 15;
            int gr = row0 + r;
            float4 v = make_float4(0.f, 0.f, 0.f, 0.f);
            if (gr < M) v = ((const float4*)(A + gr * K + kc))[kk];
            ((float4*)As)[i] = v;
        }
        __syncthreads();
#pragma unroll 8
        for (int k = 0; k < 64; k++) {
            float4 w = ((float4*)Ws)[k * 32 + c0];
#pragma unroll
            for (int i = 0; i < 8; i++) {
                float a = As[(r0 + i) * 64 + k];
                acc[i].x = fmaf(a, w.x, acc[i].x);
                acc[i].y = fmaf(a, w.y, acc[i].y);
                acc[i].z = fmaf(a, w.z, acc[i].z);
                acc[i].w = fmaf(a, w.w, acc[i].w);
            }
        }
        __syncthreads();
    }
#pragma unroll
    for (int i = 0; i < 8; i++) {
        int gr = row0 + r0 + i;
        if (gr < M) {
            float4 v = acc[i];
            if (relu) {
                v.x = fmaxf(v.x, 0.f); v.y = fmaxf(v.y, 0.f);
                v.z = fmaxf(v.z, 0.f); v.w = fmaxf(v.w, 0.f);
            }
            ((float4*)(C + gr * 128))[c0] = v;
        }
    }
}

// out[q] = relu(A[src] + B[dst]) . Wc2 + bc2     (warp per query)
__global__ void k_query(const int* __restrict__ eli, const float* __restrict__ Wc2,
                        const float* __restrict__ bc2, float* __restrict__ out, int Q) {
    int t = blockIdx.x * blockDim.x + threadIdx.x;
    int q = t >> 5, lane = t & 31;
    if (q >= Q) return;
    int s = __ldg(eli + q);
    int d = __ldg(eli + Q + q);
    float4 a = ((const float4*)g_A)[s * 32 + lane];
    float4 b = ((const float4*)g_B)[d * 32 + lane];
    float4 w = ((const float4*)Wc2)[lane];
    float ux = fmaxf(a.x + b.x, 0.f);
    float uy = fmaxf(a.y + b.y, 0.f);
    float uz = fmaxf(a.z + b.z, 0.f);
    float uw = fmaxf(a.w + b.w, 0.f);
    float sum = ux * w.x + uy * w.y + uz * w.z + uw * w.w;
#pragma unroll
    for (int o = 16; o > 0; o >>= 1) sum += __shfl_xor_sync(0xffffffffu, sum, o);
    if (lane == 0) out[q] = sum + bc2[0];
}

extern "C" void kernel_launch(void* const* d_in, const int* in_sizes, int n_in,
                              void* d_out, int out_size) {
    const float* x   = (const float*)d_in[0];
    const int*   ei  = (const int*)  d_in[1];
    const int*   eli = (const int*)  d_in[2];
    const float* W1  = (const float*)d_in[3];
    const float* b1  = (const float*)d_in[4];
    const float* W2  = (const float*)d_in[5];
    const float* b2  = (const float*)d_in[6];
    const float* Wc1 = (const float*)d_in[7];
    const float* bc1 = (const float*)d_in[8];
    const float* Wc2 = (const float*)d_in[9];
    const float* bc2 = (const float*)d_in[10];
    float* out = (float*)d_out;

    int N = in_sizes[0] / 64;
    int E = in_sizes[1] / 2;
    int Q = in_sizes[2] / 2;

    float *agg1, *h1, *agg2, *h2, *Ap, *Bp;
    cudaGetSymbolAddress((void**)&agg1, g_agg1);
    cudaGetSymbolAddress((void**)&h1,   g_h1);
    cudaGetSymbolAddress((void**)&agg2, g_agg2);
    cudaGetSymbolAddress((void**)&h2,   g_h2);
    cudaGetSymbolAddress((void**)&Ap,   g_A);
    cudaGetSymbolAddress((void**)&Bp,   g_B);

    const int B = 256;
    k_deg_init   <<<(N + B - 1) / B, B>>>(N);
    k_deg_count  <<<(E + B - 1) / B, B>>>(ei, E);
    k_dis_agg1init<<<((long)N * 16 + B - 1) / B, B>>>(x, N);
    k_scatter1   <<<((long)E * 16 + B - 1) / B, B>>>(x, ei, E);
    gemm_k<64>   <<<(N + 63) / 64, B>>>(agg1, W1, b1, h1, N, 1);
    k_agg2init   <<<((long)N * 32 + B - 1) / B, B>>>(N);
    k_scatter2   <<<((long)E * 32 + B - 1) / B, B>>>(ei, E);
    gemm_k<128>  <<<(N + 63) / 64, B>>>(agg2, W2, b2, h2, N, 0);
    gemm_k<128>  <<<(N + 63) / 64, B>>>(h2, Wc1,             bc1,     Ap, N, 0);
    gemm_k<128>  <<<(N + 63) / 64, B>>>(h2, Wc1 + 128 * 128, nullptr, Bp, N, 0);
    k_query      <<<((long)Q * 32 + B - 1) / B, B>>>(eli, Wc2, bc2, out, Q);
}

// round 4
// speedup vs baseline: 1.2884x; 1.2884x over previous
#include <cuda_runtime.h>
#include <cstdint>

#define N_NODES 50000

// ---------------- scratch (allocation-free: __device__ globals) ----------------
__device__ __align__(128) float g_deg [N_NODES];
__device__ __align__(128) float g_dis [N_NODES];
__device__ __align__(128) float g_agg1[N_NODES * 64];
__device__ __align__(128) float g_h1  [N_NODES * 128];
__device__ __align__(128) float g_agg2[N_NODES * 128];
__device__ __align__(128) float g_AB  [N_NODES * 256];   // [A | B] per node
__device__ __align__(128) float g_Wf  [128 * 256];       // W2 @ [Wc1_top | Wc1_bot]
__device__ __align__(128) float g_bf  [256];             // [b2@Wc1_top + bc1 | b2@Wc1_bot]

// ---------------- helpers ----------------
__device__ __forceinline__ uint32_t f2tf32(float f) {
    uint32_t r; asm("cvt.rna.tf32.f32 %0, %1;" : "=r"(r) : "f"(f)); return r;
}
__device__ __forceinline__ void red_add_v4(float* p, float4 v) {
    asm volatile("red.global.add.v4.f32 [%0], {%1,%2,%3,%4};"
                 :: "l"(p), "f"(v.x), "f"(v.y), "f"(v.z), "f"(v.w) : "memory");
}
__device__ __forceinline__ void mma_tf32(float* d, const uint32_t* a, uint32_t b0, uint32_t b1) {
    asm volatile(
        "mma.sync.aligned.m16n8k8.row.col.f32.tf32.tf32.f32 "
        "{%0,%1,%2,%3}, {%4,%5,%6,%7}, {%8,%9}, {%0,%1,%2,%3};"
        : "+f"(d[0]), "+f"(d[1]), "+f"(d[2]), "+f"(d[3])
        : "r"(a[0]), "r"(a[1]), "r"(a[2]), "r"(a[3]), "r"(b0), "r"(b1));
}

// ---------------- graph phase ----------------
__global__ void k_deg_init(int n) {
    int i = blockIdx.x * blockDim.x + threadIdx.x;
    if (i < n) g_deg[i] = 1.0f;
}
__global__ void k_deg_count(const int* __restrict__ row, int E) {
    int e = blockIdx.x * blockDim.x + threadIdx.x;
    if (e < E) atomicAdd(&g_deg[row[e]], 1.0f);
}
// dis = deg^-0.5 ; agg1[i] = x[i]*dis^2 (self loop folded)
__global__ void k_dis_agg1init(const float* __restrict__ x, int n) {
    int t = blockIdx.x * blockDim.x + threadIdx.x;
    int i = t >> 4, j = t & 15;
    if (i >= n) return;
    float d = rsqrtf(g_deg[i]);
    if (j == 0) g_dis[i] = d;
    float s = d * d;
    float4 v = ((const float4*)x)[i * 16 + j];
    v.x *= s; v.y *= s; v.z *= s; v.w *= s;
    ((float4*)g_agg1)[i * 16 + j] = v;
}
// agg1[col] += x[row]*dis[row]*dis[col]   (16 lanes/edge; base lane loads, shfl broadcast)
__global__ void k_scatter1(const float* __restrict__ x, const int* __restrict__ ei, int E) {
    int t = blockIdx.x * blockDim.x + threadIdx.x;
    int e = t >> 4;
    if (e >= E) return;
    int lane = threadIdx.x & 31;
    int j = lane & 15;
    int r = 0, c = 0; float nrm = 0.f;
    if (j == 0) {
        r = __ldg(ei + e);
        c = __ldg(ei + E + e);
        nrm = g_dis[r] * g_dis[c];
    }
    int src = lane & 16;
    r   = __shfl_sync(0xffffffffu, r, src);
    c   = __shfl_sync(0xffffffffu, c, src);
    nrm = __shfl_sync(0xffffffffu, nrm, src);
    float4 v = ((const float4*)x)[r * 16 + j];
    v.x *= nrm; v.y *= nrm; v.z *= nrm; v.w *= nrm;
    red_add_v4(&g_agg1[c * 64 + j * 4], v);
}
__global__ void k_agg2init(int n) {
    int t = blockIdx.x * blockDim.x + threadIdx.x;
    int i = t >> 5, j = t & 31;
    if (i >= n) return;
    float d = g_dis[i];
    float s = d * d;
    float4 v = ((const float4*)g_h1)[i * 32 + j];
    v.x *= s; v.y *= s; v.z *= s; v.w *= s;
    ((float4*)g_agg2)[i * 32 + j] = v;
}
// agg2[col] += h1[row]*nrm   (32 lanes/edge; lane0 loads, shfl broadcast)
__global__ void k_scatter2(const int* __restrict__ ei, int E) {
    int t = blockIdx.x * blockDim.x + threadIdx.x;
    int e = t >> 5;
    if (e >= E) return;
    int lane = threadIdx.x & 31;
    int r = 0, c = 0; float nrm = 0.f;
    if (lane == 0) {
        r = __ldg(ei + e);
        c = __ldg(ei + E + e);
        nrm = g_dis[r] * g_dis[c];
    }
    r   = __shfl_sync(0xffffffffu, r, 0);
    c   = __shfl_sync(0xffffffffu, c, 0);
    nrm = __shfl_sync(0xffffffffu, nrm, 0);
    float4 v = ((const float4*)g_h1)[r * 32 + lane];
    v.x *= nrm; v.y *= nrm; v.z *= nrm; v.w *= nrm;
    red_add_v4(&g_agg2[c * 128 + lane * 4], v);
}

// ---------------- fold prep ----------------
// Wf[k][n'] = sum_j W2[k][j] * Wc1[(n'>=128?128:0)+j][n'&127]     (128 x 256)
__global__ void k_foldw(const float* __restrict__ W2, const float* __restrict__ Wc1) {
    int idx = blockIdx.x * blockDim.x + threadIdx.x;
    if (idx >= 128 * 256) return;
    int k = idx >> 8, n = idx & 255;
    int which = n >> 7, nn = n & 127;
    const float* w2row = W2 + k * 128;
    const float* wc = Wc1 + (which * 128) * 128 + nn;
    float acc = 0.f;
#pragma unroll 8
    for (int j = 0; j < 128; j++) acc = fmaf(__ldg(w2row + j), __ldg(wc + j * 128), acc);
    g_Wf[idx] = acc;
}
__global__ void k_foldbias(const float* __restrict__ b2, const float* __restrict__ Wc1,
                           const float* __restrict__ bc1) {
    int n = threadIdx.x;           // 0..255
    int which = n >> 7, nn = n & 127;
    const float* wc = Wc1 + (which * 128) * 128 + nn;
    float acc = 0.f;
#pragma unroll 8
    for (int j = 0; j < 128; j++) acc = fmaf(b2[j], __ldg(wc + j * 128), acc);
    g_bf[n] = acc + (which ? 0.f : bc1[nn]);
}

// ---------------- tf32 mma.sync GEMM ----------------
// C[M, NC] = act(A[M,K] @ W[K,NC] + bias).  CTA tile 128x128, 8 warps (32x64 each).
// Smem: As[128][68] tf32, Ws[128 n][68 k] tf32 (W transposed). K chunked by 64.
#define SA 68
template <bool RELU>
__global__ __launch_bounds__(256) void gemm_mma(
    const float* __restrict__ A, const float* __restrict__ W,
    const float* __restrict__ bias, float* __restrict__ C,
    int M, int K, int NC) {
    extern __shared__ uint32_t sm[];
    uint32_t* As = sm;              // 128*68
    uint32_t* Ws = sm + 128 * SA;   // 128*68
    int tid = threadIdx.x, wid = tid >> 5, lane = tid & 31;
    int row0 = blockIdx.x * 128, col0 = blockIdx.y * 128;
    int wm = (wid & 3) * 32, wn = (wid >> 2) * 64;
    int gid = lane >> 2, tig = lane & 3;

    float acc[2][8][4];
#pragma unroll
    for (int ma = 0; ma < 2; ma++)
#pragma unroll
        for (int na = 0; na < 8; na++)
#pragma unroll
            for (int q = 0; q < 4; q++) acc[ma][na][q] = 0.f;

    int lda4 = K >> 2;
    const float4* A4 = (const float4*)A;

    for (int kc = 0; kc < K; kc += 64) {
        // A chunk: 128 rows x 64 k (as float4)
        for (int i = tid; i < 128 * 16; i += 256) {
            int r = i >> 4, kk = i & 15;
            float4 v = make_float4(0.f, 0.f, 0.f, 0.f);
            int gr = row0 + r;
            if (gr < M) v = A4[gr * lda4 + (kc >> 2) + kk];
            uint4 tv;
            tv.x = f2tf32(v.x); tv.y = f2tf32(v.y); tv.z = f2tf32(v.z); tv.w = f2tf32(v.w);
            *(uint4*)(As + r * SA + kk * 4) = tv;
        }
        // W chunk transposed: Ws[n][k]
        for (int i = tid; i < 64 * 128; i += 256) {
            int k = i >> 7, n = i & 127;
            Ws[n * SA + k] = f2tf32(__ldg(W + (kc + k) * NC + col0 + n));
        }
        __syncthreads();

        const uint32_t* a0p = As + (wm + gid) * SA;
        const uint32_t* b0p = Ws + (wn + gid) * SA;
#pragma unroll
        for (int ks = 0; ks < 64; ks += 8) {
            uint32_t afr[2][4];
#pragma unroll
            for (int ma = 0; ma < 2; ma++) {
                const uint32_t* p = a0p + ma * 16 * SA + ks + tig;
                afr[ma][0] = p[0];
                afr[ma][1] = p[8 * SA];
                afr[ma][2] = p[4];
                afr[ma][3] = p[8 * SA + 4];
            }
#pragma unroll
            for (int na = 0; na < 8; na++) {
                const uint32_t* p = b0p + na * 8 * SA + ks + tig;
                uint32_t b0 = p[0], b1 = p[4];
                mma_tf32(acc[0][na], afr[0], b0, b1);
                mma_tf32(acc[1][na], afr[1], b0, b1);
            }
        }
        __syncthreads();
    }

    // epilogue: bias + optional relu, float2 stores
#pragma unroll
    for (int ma = 0; ma < 2; ma++) {
        int r0 = row0 + wm + ma * 16 + gid;
#pragma unroll
        for (int na = 0; na < 8; na++) {
            int c = col0 + wn + na * 8 + 2 * tig;
            float bx = bias[c], by = bias[c + 1];
            float2 v0, v1;
            v0.x = acc[ma][na][0] + bx; v0.y = acc[ma][na][1] + by;
            v1.x = acc[ma][na][2] + bx; v1.y = acc[ma][na][3] + by;
            if (RELU) {
                v0.x = fmaxf(v0.x, 0.f); v0.y = fmaxf(v0.y, 0.f);
                v1.x = fmaxf(v1.x, 0.f); v1.y = fmaxf(v1.y, 0.f);
            }
            if (r0 < M)     *(float2*)(C + (long)r0 * NC + c)       = v0;
            if (r0 + 8 < M) *(float2*)(C + (long)(r0 + 8) * NC + c) = v1;
        }
    }
}

// ---------------- query ----------------
// out[q] = relu(AB[s][0:128] + AB[d][128:256]) . Wc2 + bc2   (warp/query)
__global__ void k_query(const int* __restrict__ eli, const float* __restrict__ Wc2,
                        const float* __restrict__ bc2, float* __restrict__ out, int Q) {
    int t = blockIdx.x * blockDim.x + threadIdx.x;
    int q = t >> 5, lane = t & 31;
    if (q >= Q) return;
    int s = __ldg(eli + q);
    int d = __ldg(eli + Q + q);
    float4 a = ((const float4*)g_AB)[s * 64 + lane];
    float4 b = ((const float4*)g_AB)[d * 64 + 32 + lane];
    float4 w = ((const float4*)Wc2)[lane];
    float ux = fmaxf(a.x + b.x, 0.f);
    float uy = fmaxf(a.y + b.y, 0.f);
    float uz = fmaxf(a.z + b.z, 0.f);
    float uw = fmaxf(a.w + b.w, 0.f);
    float sum = ux * w.x + uy * w.y + uz * w.z + uw * w.w;
#pragma unroll
    for (int o = 16; o > 0; o >>= 1) sum += __shfl_xor_sync(0xffffffffu, sum, o);
    if (lane == 0) out[q] = sum + bc2[0];
}

extern "C" void kernel_launch(void* const* d_in, const int* in_sizes, int n_in,
                              void* d_out, int out_size) {
    const float* x   = (const float*)d_in[0];
    const int*   ei  = (const int*)  d_in[1];
    const int*   eli = (const int*)  d_in[2];
    const float* W1  = (const float*)d_in[3];
    const float* b1  = (const float*)d_in[4];
    const float* W2  = (const float*)d_in[5];
    const float* b2  = (const float*)d_in[6];
    const float* Wc1 = (const float*)d_in[7];
    const float* bc1 = (const float*)d_in[8];
    const float* Wc2 = (const float*)d_in[9];
    const float* bc2 = (const float*)d_in[10];
    float* out = (float*)d_out;

    int N = in_sizes[0] / 64;
    int E = in_sizes[1] / 2;
    int Q = in_sizes[2] / 2;

    float *agg1, *h1, *agg2, *ABp, *Wfp, *bfp;
    cudaGetSymbolAddress((void**)&agg1, g_agg1);
    cudaGetSymbolAddress((void**)&h1,   g_h1);
    cudaGetSymbolAddress((void**)&agg2, g_agg2);
    cudaGetSymbolAddress((void**)&ABp,  g_AB);
    cudaGetSymbolAddress((void**)&Wfp,  g_Wf);
    cudaGetSymbolAddress((void**)&bfp,  g_bf);

    const int GSMEM = 2 * 128 * SA * 4;   // 69632 B
    cudaFuncSetAttribute(gemm_mma<true>,
                         cudaFuncAttributeMaxDynamicSharedMemorySize, GSMEM);
    cudaFuncSetAttribute(gemm_mma<false>,
                         cudaFuncAttributeMaxDynamicSharedMemorySize, GSMEM);

    const int B = 256;
    int gblk = (N + 127) / 128;

    k_deg_init    <<<(N + B - 1) / B, B>>>(N);
    k_deg_count   <<<(E + B - 1) / B, B>>>(ei, E);
    k_dis_agg1init<<<((long)N * 16 + B - 1) / B, B>>>(x, N);
    k_scatter1    <<<((long)E * 16 + B - 1) / B, B>>>(x, ei, E);
    k_foldw       <<<(128 * 256 + B - 1) / B, B>>>(W2, Wc1);
    k_foldbias    <<<1, 256>>>(b2, Wc1, bc1);
    gemm_mma<true> <<<dim3(gblk, 1), 256, GSMEM>>>(agg1, W1, b1, h1, N, 64, 128);
    k_agg2init    <<<((long)N * 32 + B - 1) / B, B>>>(N);
    k_scatter2    <<<((long)E * 32 + B - 1) / B, B>>>(ei, E);
    gemm_mma<false><<<dim3(gblk, 2), 256, GSMEM>>>(agg2, Wfp, bfp, ABp, N, 128, 256);
    k_query       <<<((long)Q * 32 + B - 1) / B, B>>>(eli, Wc2, bc2, out, Q);
}

// round 5
// speedup vs baseline: 1.3077x; 1.0150x over previous
#include <cuda_runtime.h>
#include <cstdint>

#define N_NODES 50000
#define E_MAX   850000

// ---------------- scratch (allocation-free: __device__ globals) ----------------
__device__ __align__(128) int   g_cntr[N_NODES];
__device__ __align__(128) int   g_cntc[N_NODES];
__device__ __align__(128) int   g_rp  [N_NODES + 1];
__device__ __align__(128) int   g_fill[N_NODES];
__device__ __align__(128) int   g_srt [E_MAX];
__device__ __align__(128) float g_dis [N_NODES];
__device__ __align__(128) float g_agg1[N_NODES * 64];
__device__ __align__(128) float g_h1  [N_NODES * 128];
__device__ __align__(128) float g_agg2[N_NODES * 128];
__device__ __align__(128) float g_AB  [N_NODES * 256];   // [A | B] per node
__device__ __align__(128) float g_Wf  [128 * 256];       // W2 @ [Wc1_top | Wc1_bot]
__device__ __align__(128) float g_bf  [256];             // [b2@Wc1_top + bc1 | b2@Wc1_bot]

// ---------------- helpers ----------------
__device__ __forceinline__ uint32_t f2tf32(float f) {
    uint32_t r; asm("cvt.rna.tf32.f32 %0, %1;" : "=r"(r) : "f"(f)); return r;
}
__device__ __forceinline__ void mma_tf32(float* d, const uint32_t* a, uint32_t b0, uint32_t b1) {
    asm volatile(
        "mma.sync.aligned.m16n8k8.row.col.f32.tf32.tf32.f32 "
        "{%0,%1,%2,%3}, {%4,%5,%6,%7}, {%8,%9}, {%0,%1,%2,%3};"
        : "+f"(d[0]), "+f"(d[1]), "+f"(d[2]), "+f"(d[3])
        : "r"(a[0]), "r"(a[1]), "r"(a[2]), "r"(a[3]), "r"(b0), "r"(b1));
}

// ---------------- CSR build ----------------
__global__ void k_zero(int n) {
    int i = blockIdx.x * blockDim.x + threadIdx.x;
    if (i < n) { g_cntr[i] = 0; g_cntc[i] = 0; }
}
__global__ void k_count(const int* __restrict__ ei, int E) {
    int e = blockIdx.x * blockDim.x + threadIdx.x;
    if (e >= E) return;
    atomicAdd(&g_cntr[__ldg(ei + e)], 1);
    atomicAdd(&g_cntc[__ldg(ei + E + e)], 1);
}
__global__ void k_dis(int n) {
    int i = blockIdx.x * blockDim.x + threadIdx.x;
    if (i < n) g_dis[i] = rsqrtf(1.0f + (float)g_cntr[i]);
}
// exclusive scan of cntc -> rp (and fill copy); single block of 1024 threads
__global__ void k_scan(int n) {
    __shared__ int ssum[1024];
    int tid = threadIdx.x;
    int chunk = (n + 1023) / 1024;
    int beg = tid * chunk, end = min(beg + chunk, n);
    int s = 0;
    for (int i = beg; i < end; i++) s += g_cntc[i];
    ssum[tid] = s;
    __syncthreads();
    for (int off = 1; off < 1024; off <<= 1) {
        int t = (tid >= off) ? ssum[tid - off] : 0;
        __syncthreads();
        ssum[tid] += t;
        __syncthreads();
    }
    int run = ssum[tid] - s;   // exclusive base for this chunk
    for (int i = beg; i < end; i++) {
        int cv = g_cntc[i];
        g_rp[i] = run; g_fill[i] = run;
        run += cv;
    }
    if (tid == 1023) g_rp[n] = run;
}
__global__ void k_permute(const int* __restrict__ ei, int E) {
    int e = blockIdx.x * blockDim.x + threadIdx.x;
    if (e >= E) return;
    int r = __ldg(ei + e);
    int c = __ldg(ei + E + e);
    int pos = atomicAdd(&g_fill[c], 1);
    g_srt[pos] = r;
}

// ---------------- gather convs (warp per node; init term folded in) ----------------
// agg1[i] = x[i]*dis_i^2 + sum_e x[src]*dis[src]*dis_i      (d=64: float2/lane)
__global__ __launch_bounds__(256) void k_gather1(const float* __restrict__ x, int n) {
    int node = blockIdx.x * 8 + (threadIdx.x >> 5);
    int lane = threadIdx.x & 31;
    if (node >= n) return;
    float di = g_dis[node];
    const float2* x2 = (const float2*)x;
    float2 acc = x2[node * 32 + lane];
    float s2 = di * di;
    acc.x *= s2; acc.y *= s2;
    int e = g_rp[node], end = g_rp[node + 1];
    for (; e + 1 < end; e += 2) {
        int s0 = __ldg(g_srt + e), s1 = __ldg(g_srt + e + 1);
        float n0 = di * __ldg(g_dis + s0);
        float n1 = di * __ldg(g_dis + s1);
        float2 v0 = x2[s0 * 32 + lane];
        float2 v1 = x2[s1 * 32 + lane];
        acc.x += v0.x * n0 + v1.x * n1;
        acc.y += v0.y * n0 + v1.y * n1;
    }
    if (e < end) {
        int s0 = __ldg(g_srt + e);
        float n0 = di * __ldg(g_dis + s0);
        float2 v0 = x2[s0 * 32 + lane];
        acc.x += v0.x * n0; acc.y += v0.y * n0;
    }
    ((float2*)g_agg1)[node * 32 + lane] = acc;
}
// agg2[i] = h1[i]*dis_i^2 + sum_e h1[src]*nrm               (d=128: float4/lane)
__global__ __launch_bounds__(256) void k_gather2(int n) {
    int node = blockIdx.x * 8 + (threadIdx.x >> 5);
    int lane = threadIdx.x & 31;
    if (node >= n) return;
    float di = g_dis[node];
    const float4* h4 = (const float4*)g_h1;
    float4 acc = h4[node * 32 + lane];
    float s2 = di * di;
    acc.x *= s2; acc.y *= s2; acc.z *= s2; acc.w *= s2;
    int e = g_rp[node], end = g_rp[node + 1];
    for (; e + 1 < end; e += 2) {
        int s0 = __ldg(g_srt + e), s1 = __ldg(g_srt + e + 1);
        float n0 = di * __ldg(g_dis + s0);
        float n1 = di * __ldg(g_dis + s1);
        float4 v0 = h4[s0 * 32 + lane];
        float4 v1 = h4[s1 * 32 + lane];
        acc.x += v0.x * n0 + v1.x * n1;
        acc.y += v0.y * n0 + v1.y * n1;
        acc.z += v0.z * n0 + v1.z * n1;
        acc.w += v0.w * n0 + v1.w * n1;
    }
    if (e < end) {
        int s0 = __ldg(g_srt + e);
        float n0 = di * __ldg(g_dis + s0);
        float4 v0 = h4[s0 * 32 + lane];
        acc.x += v0.x * n0; acc.y += v0.y * n0;
        acc.z += v0.z * n0; acc.w += v0.w * n0;
    }
    ((float4*)g_agg2)[node * 32 + lane] = acc;
}

// ---------------- fold prep ----------------
__global__ void k_foldw(const float* __restrict__ W2, const float* __restrict__ Wc1) {
    int idx = blockIdx.x * blockDim.x + threadIdx.x;
    if (idx >= 128 * 256) return;
    int k = idx >> 8, n = idx & 255;
    int which = n >> 7, nn = n & 127;
    const float* w2row = W2 + k * 128;
    const float* wc = Wc1 + (which * 128) * 128 + nn;
    float acc = 0.f;
#pragma unroll 8
    for (int j = 0; j < 128; j++) acc = fmaf(__ldg(w2row + j), __ldg(wc + j * 128), acc);
    g_Wf[idx] = acc;
}
__global__ void k_foldbias(const float* __restrict__ b2, const float* __restrict__ Wc1,
                           const float* __restrict__ bc1) {
    int n = threadIdx.x;           // 0..255
    int which = n >> 7, nn = n & 127;
    const float* wc = Wc1 + (which * 128) * 128 + nn;
    float acc = 0.f;
#pragma unroll 8
    for (int j = 0; j < 128; j++) acc = fmaf(b2[j], __ldg(wc + j * 128), acc);
    g_bf[n] = acc + (which ? 0.f : bc1[nn]);
}

// ---------------- tf32 mma.sync GEMM ----------------
// C[M, NC] = act(A[M,K] @ W[K,NC] + bias).  CTA tile 128x128, 8 warps (32x64 each).
#define SA 68
template <bool RELU>
__global__ __launch_bounds__(256) void gemm_mma(
    const float* __restrict__ A, const float* __restrict__ W,
    const float* __restrict__ bias, float* __restrict__ C,
    int M, int K, int NC) {
    extern __shared__ uint32_t sm[];
    uint32_t* As = sm;              // 128*68
    uint32_t* Ws = sm + 128 * SA;   // 128*68
    int tid = threadIdx.x, wid = tid >> 5, lane = tid & 31;
    int row0 = blockIdx.x * 128, col0 = blockIdx.y * 128;
    int wm = (wid & 3) * 32, wn = (wid >> 2) * 64;
    int gid = lane >> 2, tig = lane & 3;

    float acc[2][8][4];
#pragma unroll
    for (int ma = 0; ma < 2; ma++)
#pragma unroll
        for (int na = 0; na < 8; na++)
#pragma unroll
            for (int q = 0; q < 4; q++) acc[ma][na][q] = 0.f;

    int lda4 = K >> 2;
    const float4* A4 = (const float4*)A;

    for (int kc = 0; kc < K; kc += 64) {
        for (int i = tid; i < 128 * 16; i += 256) {
            int r = i >> 4, kk = i & 15;
            float4 v = make_float4(0.f, 0.f, 0.f, 0.f);
            int gr = row0 + r;
            if (gr < M) v = A4[gr * lda4 + (kc >> 2) + kk];
            uint4 tv;
            tv.x = f2tf32(v.x); tv.y = f2tf32(v.y); tv.z = f2tf32(v.z); tv.w = f2tf32(v.w);
            *(uint4*)(As + r * SA + kk * 4) = tv;
        }
        for (int i = tid; i < 64 * 128; i += 256) {
            int k = i >> 7, n = i & 127;
            Ws[n * SA + k] = f2tf32(__ldg(W + (kc + k) * NC + col0 + n));
        }
        __syncthreads();

        const uint32_t* a0p = As + (wm + gid) * SA;
        const uint32_t* b0p = Ws + (wn + gid) * SA;
#pragma unroll
        for (int ks = 0; ks < 64; ks += 8) {
            uint32_t afr[2][4];
#pragma unroll
            for (int ma = 0; ma < 2; ma++) {
                const uint32_t* p = a0p + ma * 16 * SA + ks + tig;
                afr[ma][0] = p[0];
                afr[ma][1] = p[8 * SA];
                afr[ma][2] = p[4];
                afr[ma][3] = p[8 * SA + 4];
            }
#pragma unroll
            for (int na = 0; na < 8; na++) {
                const uint32_t* p = b0p + na * 8 * SA + ks + tig;
                uint32_t b0 = p[0], b1 = p[4];
                mma_tf32(acc[0][na], afr[0], b0, b1);
                mma_tf32(acc[1][na], afr[1], b0, b1);
            }
        }
        __syncthreads();
    }

#pragma unroll
    for (int ma = 0; ma < 2; ma++) {
        int r0 = row0 + wm + ma * 16 + gid;
#pragma unroll
        for (int na = 0; na < 8; na++) {
            int c = col0 + wn + na * 8 + 2 * tig;
            float bx = bias[c], by = bias[c + 1];
            float2 v0, v1;
            v0.x = acc[ma][na][0] + bx; v0.y = acc[ma][na][1] + by;
            v1.x = acc[ma][na][2] + bx; v1.y = acc[ma][na][3] + by;
            if (RELU) {
                v0.x = fmaxf(v0.x, 0.f); v0.y = fmaxf(v0.y, 0.f);
                v1.x = fmaxf(v1.x, 0.f); v1.y = fmaxf(v1.y, 0.f);
            }
            if (r0 < M)     *(float2*)(C + (long)r0 * NC + c)       = v0;
            if (r0 + 8 < M) *(float2*)(C + (long)(r0 + 8) * NC + c) = v1;
        }
    }
}

// ---------------- query ----------------
__global__ void k_query(const int* __restrict__ eli, const float* __restrict__ Wc2,
                        const float* __restrict__ bc2, float* __restrict__ out, int Q) {
    int t = blockIdx.x * blockDim.x + threadIdx.x;
    int q = t >> 5, lane = t & 31;
    if (q >= Q) return;
    int s = __ldg(eli + q);
    int d = __ldg(eli + Q + q);
    float4 a = ((const float4*)g_AB)[s * 64 + lane];
    float4 b = ((const float4*)g_AB)[d * 64 + 32 + lane];
    float4 w = ((const float4*)Wc2)[lane];
    float ux = fmaxf(a.x + b.x, 0.f);
    float uy = fmaxf(a.y + b.y, 0.f);
    float uz = fmaxf(a.z + b.z, 0.f);
    float uw = fmaxf(a.w + b.w, 0.f);
    float sum = ux * w.x + uy * w.y + uz * w.z + uw * w.w;
#pragma unroll
    for (int o = 16; o > 0; o >>= 1) sum += __shfl_xor_sync(0xffffffffu, sum, o);
    if (lane == 0) out[q] = sum + bc2[0];
}

extern "C" void kernel_launch(void* const* d_in, const int* in_sizes, int n_in,
                              void* d_out, int out_size) {
    const float* x   = (const float*)d_in[0];
    const int*   ei  = (const int*)  d_in[1];
    const int*   eli = (const int*)  d_in[2];
    const float* W1  = (const float*)d_in[3];
    const float* b1  = (const float*)d_in[4];
    const float* W2  = (const float*)d_in[5];
    const float* b2  = (const float*)d_in[6];
    const float* Wc1 = (const float*)d_in[7];
    const float* bc1 = (const float*)d_in[8];
    const float* Wc2 = (const float*)d_in[9];
    const float* bc2 = (const float*)d_in[10];
    float* out = (float*)d_out;

    int N = in_sizes[0] / 64;
    int E = in_sizes[1] / 2;
    int Q = in_sizes[2] / 2;

    float *agg1, *h1, *ABp, *Wfp, *bfp;
    cudaGetSymbolAddress((void**)&agg1, g_agg1);
    cudaGetSymbolAddress((void**)&h1,   g_h1);
    cudaGetSymbolAddress((void**)&ABp,  g_AB);
    cudaGetSymbolAddress((void**)&Wfp,  g_Wf);
    cudaGetSymbolAddress((void**)&bfp,  g_bf);
    float* agg2;
    cudaGetSymbolAddress((void**)&agg2, g_agg2);

    const int GSMEM = 2 * 128 * SA * 4;   // 69632 B
    cudaFuncSetAttribute(gemm_mma<true>,
                         cudaFuncAttributeMaxDynamicSharedMemorySize, GSMEM);
    cudaFuncSetAttribute(gemm_mma<false>,
                         cudaFuncAttributeMaxDynamicSharedMemorySize, GSMEM);

    const int B = 256;
    int gblk = (N + 127) / 128;
    int nwarp_blk = (N + 7) / 8;

    // CSR build
    k_zero    <<<(N + B - 1) / B, B>>>(N);
    k_count   <<<(E + B - 1) / B, B>>>(ei, E);
    k_dis     <<<(N + B - 1) / B, B>>>(N);
    k_scan    <<<1, 1024>>>(N);
    k_permute <<<(E + B - 1) / B, B>>>(ei, E);
    // weight fold prep (independent of graph)
    k_foldw   <<<(128 * 256 + B - 1) / B, B>>>(W2, Wc1);
    k_foldbias<<<1, 256>>>(b2, Wc1, bc1);
    // conv1
    k_gather1 <<<nwarp_blk, B>>>(x, N);
    gemm_mma<true> <<<dim3(gblk, 1), 256, GSMEM>>>(agg1, W1, b1, h1, N, 64, 128);
    // conv2 (+ folded classifier layer 1)
    k_gather2 <<<nwarp_blk, B>>>(N);
    gemm_mma<false><<<dim3(gblk, 2), 256, GSMEM>>>(agg2, Wfp, bfp, ABp, N, 128, 256);
    // query
    k_query   <<<((long)Q * 32 + B - 1) / B, B>>>(eli, Wc2, bc2, out, Q);
}

// round 6
// speedup vs baseline: 1.7425x; 1.3325x over previous
#include <cuda_runtime.h>
#include <cstdint>

#define N_NODES 50000
#define E_MAX   850000
#define SCAN_B  1024
#define SCAN_G  ((N_NODES + SCAN_B - 1) / SCAN_B)   // 49

// ---------------- scratch (allocation-free: __device__ globals) ----------------
__device__ __align__(128) int   g_cntr[N_NODES];
__device__ __align__(128) int   g_cntc[N_NODES];
__device__ __align__(128) int   g_rp  [N_NODES + 1];
__device__ __align__(128) int   g_fill[N_NODES];
__device__ __align__(128) int   g_bsum[SCAN_G];
__device__ __align__(128) int   g_boff[SCAN_G];
__device__ __align__(128) int   g_srt [E_MAX];
__device__ __align__(128) float g_dis [N_NODES];
__device__ __align__(128) float g_agg1[N_NODES * 64];
__device__ __align__(128) float g_h1  [N_NODES * 128];
__device__ __align__(128) float g_agg2[N_NODES * 128];
__device__ __align__(128) float g_AB  [N_NODES * 256];   // [A | B] per node
__device__ __align__(128) float g_Wf  [128 * 256];       // W2 @ [Wc1_top | Wc1_bot]
__device__ __align__(128) float g_bf  [256];             // [b2@Wc1_top + bc1 | b2@Wc1_bot]

// ---------------- helpers ----------------
__device__ __forceinline__ uint32_t f2tf32(float f) {
    uint32_t r; asm("cvt.rna.tf32.f32 %0, %1;" : "=r"(r) : "f"(f)); return r;
}
__device__ __forceinline__ void mma_tf32(float* d, const uint32_t* a, uint32_t b0, uint32_t b1) {
    asm volatile(
        "mma.sync.aligned.m16n8k8.row.col.f32.tf32.tf32.f32 "
        "{%0,%1,%2,%3}, {%4,%5,%6,%7}, {%8,%9}, {%0,%1,%2,%3};"
        : "+f"(d[0]), "+f"(d[1]), "+f"(d[2]), "+f"(d[3])
        : "r"(a[0]), "r"(a[1]), "r"(a[2]), "r"(a[3]), "r"(b0), "r"(b1));
}

// ---------------- CSR build ----------------
__global__ void k_zero(int n) {
    int i = blockIdx.x * blockDim.x + threadIdx.x;
    if (i < n) { g_cntr[i] = 0; g_cntc[i] = 0; }
}
__global__ void k_count(const int* __restrict__ ei, int E) {
    int e = blockIdx.x * blockDim.x + threadIdx.x;
    if (e >= E) return;
    atomicAdd(&g_cntr[__ldg(ei + e)], 1);
    atomicAdd(&g_cntc[__ldg(ei + E + e)], 1);
}
__global__ void k_dis(int n) {
    int i = blockIdx.x * blockDim.x + threadIdx.x;
    if (i < n) g_dis[i] = rsqrtf(1.0f + (float)g_cntr[i]);
}

// phase 1: per-block exclusive scan of cntc (1024/block), block total -> g_bsum
__global__ __launch_bounds__(SCAN_B) void k_scan_blk(int n) {
    __shared__ int wsum[32];
    int tid = threadIdx.x, lane = tid & 31, wid = tid >> 5;
    int i = blockIdx.x * SCAN_B + tid;
    int v = (i < n) ? g_cntc[i] : 0;
    // warp inclusive scan
    int s = v;
#pragma unroll
    for (int o = 1; o < 32; o <<= 1) {
        int t = __shfl_up_sync(0xffffffffu, s, o);
        if (lane >= o) s += t;
    }
    if (lane == 31) wsum[wid] = s;
    __syncthreads();
    if (wid == 0) {
        int ws = (lane < 32) ? wsum[lane] : 0;
#pragma unroll
        for (int o = 1; o < 32; o <<= 1) {
            int t = __shfl_up_sync(0xffffffffu, ws, o);
            if (lane >= o) ws += t;
        }
        wsum[lane] = ws;
    }
    __syncthreads();
    int incl = s + (wid ? wsum[wid - 1] : 0);
    if (i < n) g_rp[i] = incl - v;                 // block-local exclusive
    if (tid == SCAN_B - 1) g_bsum[blockIdx.x] = incl;
}
// phase 2: exclusive scan of block sums (one warp-ish block)
__global__ void k_scan_top(int nblk, int n) {
    int tid = threadIdx.x;   // 64 threads >= nblk(49)
    int v = (tid < nblk) ? g_bsum[tid] : 0;
    int s = v;
#pragma unroll
    for (int o = 1; o < 64; o <<= 1) {
        int t = __shfl_up_sync(0xffffffffu, s, o & 31);
        if ((tid & 31) >= (o & 31) && o < 32) s += t;
    }
    // simpler: do a shared-memory scan (64 elems) to avoid cross-warp shfl issues
    __shared__ int sh[64];
    sh[tid] = v;
    __syncthreads();
    for (int o = 1; o < 64; o <<= 1) {
        int t = (tid >= o) ? sh[tid - o] : 0;
        __syncthreads();
        sh[tid] += t;
        __syncthreads();
    }
    if (tid < nblk) g_boff[tid] = sh[tid] - v;
    if (tid == nblk - 1) g_rp[n] = sh[tid];
}
// phase 3: add block offsets, copy to fill
__global__ __launch_bounds__(SCAN_B) void k_scan_add(int n) {
    int i = blockIdx.x * SCAN_B + threadIdx.x;
    if (i >= n) return;
    int v = g_rp[i] + g_boff[blockIdx.x];
    g_rp[i] = v;
    g_fill[i] = v;
}
__global__ void k_permute(const int* __restrict__ ei, int E) {
    int e = blockIdx.x * blockDim.x + threadIdx.x;
    if (e >= E) return;
    int r = __ldg(ei + e);
    int c = __ldg(ei + E + e);
    int pos = atomicAdd(&g_fill[c], 1);
    g_srt[pos] = r;
}

// ---------------- gather convs (warp per node; init term folded in) ----------------
__global__ __launch_bounds__(256) void k_gather1(const float* __restrict__ x, int n) {
    int node = blockIdx.x * 8 + (threadIdx.x >> 5);
    int lane = threadIdx.x & 31;
    if (node >= n) return;
    float di = g_dis[node];
    const float2* x2 = (const float2*)x;
    float2 acc = x2[node * 32 + lane];
    float s2 = di * di;
    acc.x *= s2; acc.y *= s2;
    int e = g_rp[node], end = g_rp[node + 1];
    for (; e + 1 < end; e += 2) {
        int s0 = __ldg(g_srt + e), s1 = __ldg(g_srt + e + 1);
        float n0 = di * __ldg(g_dis + s0);
        float n1 = di * __ldg(g_dis + s1);
        float2 v0 = x2[s0 * 32 + lane];
        float2 v1 = x2[s1 * 32 + lane];
        acc.x += v0.x * n0 + v1.x * n1;
        acc.y += v0.y * n0 + v1.y * n1;
    }
    if (e < end) {
        int s0 = __ldg(g_srt + e);
        float n0 = di * __ldg(g_dis + s0);
        float2 v0 = x2[s0 * 32 + lane];
        acc.x += v0.x * n0; acc.y += v0.y * n0;
    }
    ((float2*)g_agg1)[node * 32 + lane] = acc;
}
__global__ __launch_bounds__(256) void k_gather2(int n) {
    int node = blockIdx.x * 8 + (threadIdx.x >> 5);
    int lane = threadIdx.x & 31;
    if (node >= n) return;
    float di = g_dis[node];
    const float4* h4 = (const float4*)g_h1;
    float4 acc = h4[node * 32 + lane];
    float s2 = di * di;
    acc.x *= s2; acc.y *= s2; acc.z *= s2; acc.w *= s2;
    int e = g_rp[node], end = g_rp[node + 1];
    for (; e + 1 < end; e += 2) {
        int s0 = __ldg(g_srt + e), s1 = __ldg(g_srt + e + 1);
        float n0 = di * __ldg(g_dis + s0);
        float n1 = di * __ldg(g_dis + s1);
        float4 v0 = h4[s0 * 32 + lane];
        float4 v1 = h4[s1 * 32 + lane];
        acc.x += v0.x * n0 + v1.x * n1;
        acc.y += v0.y * n0 + v1.y * n1;
        acc.z += v0.z * n0 + v1.z * n1;
        acc.w += v0.w * n0 + v1.w * n1;
    }
    if (e < end) {
        int s0 = __ldg(g_srt + e);
        float n0 = di * __ldg(g_dis + s0);
        float4 v0 = h4[s0 * 32 + lane];
        acc.x += v0.x * n0; acc.y += v0.y * n0;
        acc.z += v0.z * n0; acc.w += v0.w * n0;
    }
    ((float4*)g_agg2)[node * 32 + lane] = acc;
}

// ---------------- fold prep ----------------
__global__ void k_foldw(const float* __restrict__ W2, const float* __restrict__ Wc1) {
    int idx = blockIdx.x * blockDim.x + threadIdx.x;
    if (idx >= 128 * 256) return;
    int k = idx >> 8, n = idx & 255;
    int which = n >> 7, nn = n & 127;
    const float* w2row = W2 + k * 128;
    const float* wc = Wc1 + (which * 128) * 128 + nn;
    float acc = 0.f;
#pragma unroll 8
    for (int j = 0; j < 128; j++) acc = fmaf(__ldg(w2row + j), __ldg(wc + j * 128), acc);
    g_Wf[idx] = acc;
}
__global__ void k_foldbias(const float* __restrict__ b2, const float* __restrict__ Wc1,
                           const float* __restrict__ bc1) {
    int n = threadIdx.x;           // 0..255
    int which = n >> 7, nn = n & 127;
    const float* wc = Wc1 + (which * 128) * 128 + nn;
    float acc = 0.f;
#pragma unroll 8
    for (int j = 0; j < 128; j++) acc = fmaf(b2[j], __ldg(wc + j * 128), acc);
    g_bf[n] = acc + (which ? 0.f : bc1[nn]);
}

// ---------------- tf32 mma.sync GEMM ----------------
#define SA 68
template <bool RELU>
__global__ __launch_bounds__(256) void gemm_mma(
    const float* __restrict__ A, const float* __restrict__ W,
    const float* __restrict__ bias, float* __restrict__ C,
    int M, int K, int NC) {
    extern __shared__ uint32_t sm[];
    uint32_t* As = sm;              // 128*68
    uint32_t* Ws = sm + 128 * SA;   // 128*68
    int tid = threadIdx.x, wid = tid >> 5, lane = tid & 31;
    int row0 = blockIdx.x * 128, col0 = blockIdx.y * 128;
    int wm = (wid & 3) * 32, wn = (wid >> 2) * 64;
    int gid = lane >> 2, tig = lane & 3;

    float acc[2][8][4];
#pragma unroll
    for (int ma = 0; ma < 2; ma++)
#pragma unroll
        for (int na = 0; na < 8; na++)
#pragma unroll
            for (int q = 0; q < 4; q++) acc[ma][na][q] = 0.f;

    int lda4 = K >> 2;
    const float4* A4 = (const float4*)A;

    for (int kc = 0; kc < K; kc += 64) {
        for (int i = tid; i < 128 * 16; i += 256) {
            int r = i >> 4, kk = i & 15;
            float4 v = make_float4(0.f, 0.f, 0.f, 0.f);
            int gr = row0 + r;
            if (gr < M) v = A4[gr * lda4 + (kc >> 2) + kk];
            uint4 tv;
            tv.x = f2tf32(v.x); tv.y = f2tf32(v.y); tv.z = f2tf32(v.z); tv.w = f2tf32(v.w);
            *(uint4*)(As + r * SA + kk * 4) = tv;
        }
        for (int i = tid; i < 64 * 128; i += 256) {
            int k = i >> 7, n = i & 127;
            Ws[n * SA + k] = f2tf32(__ldg(W + (kc + k) * NC + col0 + n));
        }
        __syncthreads();

        const uint32_t* a0p = As + (wm + gid) * SA;
        const uint32_t* b0p = Ws + (wn + gid) * SA;
#pragma unroll
        for (int ks = 0; ks < 64; ks += 8) {
            uint32_t afr[2][4];
#pragma unroll
            for (int ma = 0; ma < 2; ma++) {
                const uint32_t* p = a0p + ma * 16 * SA + ks + tig;
                afr[ma][0] = p[0];
                afr[ma][1] = p[8 * SA];
                afr[ma][2] = p[4];
                afr[ma][3] = p[8 * SA + 4];
            }
#pragma unroll
            for (int na = 0; na < 8; na++) {
                const uint32_t* p = b0p + na * 8 * SA + ks + tig;
                uint32_t b0 = p[0], b1 = p[4];
                mma_tf32(acc[0][na], afr[0], b0, b1);
                mma_tf32(acc[1][na], afr[1], b0, b1);
            }
        }
        __syncthreads();
    }

#pragma unroll
    for (int ma = 0; ma < 2; ma++) {
        int r0 = row0 + wm + ma * 16 + gid;
#pragma unroll
        for (int na = 0; na < 8; na++) {
            int c = col0 + wn + na * 8 + 2 * tig;
            float bx = bias[c], by = bias[c + 1];
            float2 v0, v1;
            v0.x = acc[ma][na][0] + bx; v0.y = acc[ma][na][1] + by;
            v1.x = acc[ma][na][2] + bx; v1.y = acc[ma][na][3] + by;
            if (RELU) {
                v0.x = fmaxf(v0.x, 0.f); v0.y = fmaxf(v0.y, 0.f);
                v1.x = fmaxf(v1.x, 0.f); v1.y = fmaxf(v1.y, 0.f);
            }
            if (r0 < M)     *(float2*)(C + (long)r0 * NC + c)       = v0;
            if (r0 + 8 < M) *(float2*)(C + (long)(r0 + 8) * NC + c) = v1;
        }
    }
}

// ---------------- query ----------------
__global__ void k_query(const int* __restrict__ eli, const float* __restrict__ Wc2,
                        const float* __restrict__ bc2, float* __restrict__ out, int Q) {
    int t = blockIdx.x * blockDim.x + threadIdx.x;
    int q = t >> 5, lane = t & 31;
    if (q >= Q) return;
    int s = __ldg(eli + q);
    int d = __ldg(eli + Q + q);
    float4 a = ((const float4*)g_AB)[s * 64 + lane];
    float4 b = ((const float4*)g_AB)[d * 64 + 32 + lane];
    float4 w = ((const float4*)Wc2)[lane];
    float ux = fmaxf(a.x + b.x, 0.f);
    float uy = fmaxf(a.y + b.y, 0.f);
    float uz = fmaxf(a.z + b.z, 0.f);
    float uw = fmaxf(a.w + b.w, 0.f);
    float sum = ux * w.x + uy * w.y + uz * w.z + uw * w.w;
#pragma unroll
    for (int o = 16; o > 0; o >>= 1) sum += __shfl_xor_sync(0xffffffffu, sum, o);
    if (lane == 0) out[q] = sum + bc2[0];
}

extern "C" void kernel_launch(void* const* d_in, const int* in_sizes, int n_in,
                              void* d_out, int out_size) {
    const float* x   = (const float*)d_in[0];
    const int*   ei  = (const int*)  d_in[1];
    const int*   eli = (const int*)  d_in[2];
    const float* W1  = (const float*)d_in[3];
    const float* b1  = (const float*)d_in[4];
    const float* W2  = (const float*)d_in[5];
    const float* b2  = (const float*)d_in[6];
    const float* Wc1 = (const float*)d_in[7];
    const float* bc1 = (const float*)d_in[8];
    const float* Wc2 = (const float*)d_in[9];
    const float* bc2 = (const float*)d_in[10];
    float* out = (float*)d_out;

    int N = in_sizes[0] / 64;
    int E = in_sizes[1] / 2;
    int Q = in_sizes[2] / 2;

    float *agg1, *h1, *ABp, *Wfp, *bfp, *agg2;
    cudaGetSymbolAddress((void**)&agg1, g_agg1);
    cudaGetSymbolAddress((void**)&h1,   g_h1);
    cudaGetSymbolAddress((void**)&ABp,  g_AB);
    cudaGetSymbolAddress((void**)&Wfp,  g_Wf);
    cudaGetSymbolAddress((void**)&bfp,  g_bf);
    cudaGetSymbolAddress((void**)&agg2, g_agg2);

    const int GSMEM = 2 * 128 * SA * 4;   // 69632 B
    cudaFuncSetAttribute(gemm_mma<true>,
                         cudaFuncAttributeMaxDynamicSharedMemorySize, GSMEM);
    cudaFuncSetAttribute(gemm_mma<false>,
                         cudaFuncAttributeMaxDynamicSharedMemorySize, GSMEM);

    const int B = 256;
    int gblk = (N + 127) / 128;
    int nwarp_blk = (N + 7) / 8;
    int scan_g = (N + SCAN_B - 1) / SCAN_B;

    // CSR build
    k_zero    <<<(N + B - 1) / B, B>>>(N);
    k_count   <<<(E + B - 1) / B, B>>>(ei, E);
    k_dis     <<<(N + B - 1) / B, B>>>(N);
    k_scan_blk<<<scan_g, SCAN_B>>>(N);
    k_scan_top<<<1, 64>>>(scan_g, N);
    k_scan_add<<<scan_g, SCAN_B>>>(N);
    k_permute <<<(E + B - 1) / B, B>>>(ei, E);
    // weight fold prep (independent of graph)
    k_foldw   <<<(128 * 256 + B - 1) / B, B>>>(W2, Wc1);
    k_foldbias<<<1, 256>>>(b2, Wc1, bc1);
    // conv1
    k_gather1 <<<nwarp_blk, B>>>(x, N);
    gemm_mma<true> <<<dim3(gblk, 1), 256, GSMEM>>>(agg1, W1, b1, h1, N, 64, 128);
    // conv2 (+ folded classifier layer 1)
    k_gather2 <<<nwarp_blk, B>>>(N);
    gemm_mma<false><<<dim3(gblk, 2), 256, GSMEM>>>(agg2, Wfp, bfp, ABp, N, 128, 256);
    // query
    k_query   <<<((long)Q * 32 + B - 1) / B, B>>>(eli, Wc2, bc2, out, Q);
}